// round 14
// baseline (speedup 1.0000x reference)
#include <cuda_runtime.h>

// Problem constants (fixed by the reference)
constexpr int H_   = 1024;
constexpr int W_   = 1024;
constexpr int FID_ = 100;
constexpr int NF_  = 8;
constexpr int NPTS = 1 << 20;
constexpr int KST  = 20;

// Pixel-interleaved accumulator: [H*W] x float4. 16 MB, L2-resident.
// Zero-initialized at module load; finalize_kernel re-zeros it after reading,
// so it is zero at the start of EVERY kernel_launch call (correctness run and
// each graph replay alike) — no separate zeroing pass needed.
__device__ float4 g_acc[H_ * W_];

__device__ __forceinline__ void red_add_v4(float4* addr, float4 v) {
    // sm_90+ vector float reduction: one op for all 4 channels.
    asm volatile("red.global.add.v4.f32 [%0], {%1,%2,%3,%4};"
                 :: "l"(addr), "f"(v.x), "f"(v.y), "f"(v.z), "f"(v.w)
                 : "memory");
}

__global__ __launch_bounds__(256) void flame_kernel(
    const float* __restrict__ points,      // [NPTS,3] (x,y,c)
    const int*   __restrict__ choices,     // [KST, NPTS]
    const float* __restrict__ A,           // [NF,2,2]
    const float* __restrict__ Bv,          // [NF,2]
    const float* __restrict__ fcol,        // [NF]
    const float* __restrict__ pal,         // [FID+1,4]
    const float* __restrict__ minv,        // [2]
    const float* __restrict__ rngv,        // [2]
    const int*   __restrict__ skipp)       // [1]
{
    __shared__ float4 sA[NF_];             // a00,a01,a10,a11
    __shared__ float4 sBC[NF_];            // bx,by,func_color,pad — R13 change:
                                           // 2 table LDS/iter instead of 3
    __shared__ float4 sP[FID_ + 1];

    const int t = threadIdx.x;
    if (t < NF_) {
        sA[t]  = make_float4(A[4*t], A[4*t+1], A[4*t+2], A[4*t+3]);
        sBC[t] = make_float4(Bv[2*t], Bv[2*t+1], fcol[t], 0.f);
    }
    for (int i = t; i <= FID_; i += blockDim.x)
        sP[i] = make_float4(pal[4*i], pal[4*i+1], pal[4*i+2], pal[4*i+3]);

    const float mnx = minv[0], mny = minv[1];
    const float rx  = rngv[0], ry  = rngv[1];
    const int skip  = skipp[0];
    __syncthreads();

    const int n = blockIdx.x * blockDim.x + t;
    float x = points[3*n + 0];
    float y = points[3*n + 1];
    float c = points[3*n + 2];

    #pragma unroll
    for (int k = 0; k < KST; k++) {
        // Per-iteration coalesced load (front-batching regressed — R2).
        // __ldcs: choices streamed once (80 MB) — evict-first spares L1/L2
        // capacity for the RED traffic.
        const int idx    = __ldcs(&choices[k * NPTS + n]);
        const float4 a   = sA[idx];
        const float4 bfc = sBC[idx];
        // Exact FP expression order / identical values — bit-identical result.
        const float nx = a.x * x + a.y * y + bfc.x;
        const float ny = a.z * x + a.w * y + bfc.y;
        c = 0.5f * (c + bfc.z);
        x = nx; y = ny;

        if (k < skip) continue;

        // Matches XLA astype(int32): truncate toward zero, saturating, NaN->0.
        const int xb = (int)((x - mnx) * rx);
        const int yb = (int)((y - mny) * ry);
        if ((unsigned)xb < (unsigned)W_ && (unsigned)yb < (unsigned)H_) {
            const float _c = c * (float)FID_;
            const float cf = floorf(_c);
            const float t1 = _c - cf;
            const float t0 = 1.0f - t1;
            int cfi = (int)cf;  cfi = max(0, min(FID_, cfi));
            // ceil(_c) == floor(_c)+1 except when _c integral, where t1==0
            // zeroes the t1*p1 term either way -> bit-identical.
            const int cci = min(FID_, cfi + 1);
            const float4 p0 = sP[cfi];
            const float4 p1 = sP[cci];
            float4 v;
            v.x = t1 * p1.x + t0 * p0.x;
            v.y = t1 * p1.y + t0 * p0.y;
            v.z = t1 * p1.z + t0 * p0.z;
            v.w = t1 * p1.w + t0 * p0.w;
            // img[:, xb, yb]: xb indexes dim of size H (stride W), yb last dim
            red_add_v4(&g_acc[xb * W_ + yb], v);
        }
    }
}

// Loads-first / stores-last (R7 lesson: interleaving the re-zero store
// collapsed MLP, 9.4 -> 32.8us). raw0/out streaming marked evict-first
// (neutral in R13 but protects g_acc residency at zero cost).
__global__ __launch_bounds__(256) void finalize_kernel(
    const float* __restrict__ raw0,
    float* __restrict__ out) {
    const int p = blockIdx.x * blockDim.x + threadIdx.x;
    // --- all loads issue first ---
    const float4 v = g_acc[p];
    const float r0 = __ldcs(&raw0[p + 0 * H_ * W_]);
    const float r1 = __ldcs(&raw0[p + 1 * H_ * W_]);
    const float r2 = __ldcs(&raw0[p + 2 * H_ * W_]);
    const float r3 = __ldcs(&raw0[p + 3 * H_ * W_]);
    // --- then stores (evict-first: out is write-once) ---
    __stcs(&out[p + 0 * H_ * W_], v.x + r0);
    __stcs(&out[p + 1 * H_ * W_], v.y + r1);
    __stcs(&out[p + 2 * H_ * W_], v.z + r2);
    __stcs(&out[p + 3 * H_ * W_], v.w + r3);
    // Re-zero for the next invocation (replaces the 6us zeroing pass).
    g_acc[p] = make_float4(0.f, 0.f, 0.f, 0.f);
}

extern "C" void kernel_launch(void* const* d_in, const int* in_sizes, int n_in,
                              void* d_out, int out_size) {
    const float* points = (const float*)d_in[0];
    const int*   choices= (const int*)  d_in[1];
    const float* A      = (const float*)d_in[2];
    const float* b      = (const float*)d_in[3];
    const float* fcol   = (const float*)d_in[4];
    const float* pal    = (const float*)d_in[5];
    const float* minv   = (const float*)d_in[6];
    const float* rngv   = (const float*)d_in[7];
    const float* raw0   = (const float*)d_in[8];
    const int*   skip   = (const int*)  d_in[9];
    float* out = (float*)d_out;

    // No zeroing pass: g_acc starts zeroed (module load) and finalize_kernel
    // restores the all-zero state at the end of every call.
    flame_kernel<<<NPTS / 256, 256>>>(points, choices, A, b, fcol, pal,
                                      minv, rngv, skip);
    finalize_kernel<<<(H_ * W_) / 256, 256>>>(raw0, out);
}

// round 15
// speedup vs baseline: 1.0381x; 1.0381x over previous
#include <cuda_runtime.h>

// Problem constants (fixed by the reference)
constexpr int H_   = 1024;
constexpr int W_   = 1024;
constexpr int FID_ = 100;
constexpr int NF_  = 8;
constexpr int NPTS = 1 << 20;
constexpr int KST  = 20;

// Pixel-interleaved accumulator: [H*W] x float4. 16 MB, L2-resident.
// Zero-initialized at module load; finalize_kernel re-zeros it after reading,
// so it is zero at the start of EVERY kernel_launch call (correctness run and
// each graph replay alike) — no separate zeroing pass needed.
__device__ float4 g_acc[H_ * W_];

__device__ __forceinline__ void red_add_v4(float4* addr, float4 v) {
    // sm_90+ vector float reduction: one op for all 4 channels.
    asm volatile("red.global.add.v4.f32 [%0], {%1,%2,%3,%4};"
                 :: "l"(addr), "f"(v.x), "f"(v.y), "f"(v.z), "f"(v.w)
                 : "memory");
}

constexpr int FLAME_BLK = 128;   // R14 experiment: finer CTA grain (was 256)

__global__ __launch_bounds__(FLAME_BLK) void flame_kernel(
    const float* __restrict__ points,      // [NPTS,3] (x,y,c)
    const int*   __restrict__ choices,     // [KST, NPTS]
    const float* __restrict__ A,           // [NF,2,2]
    const float* __restrict__ Bv,          // [NF,2]
    const float* __restrict__ fcol,        // [NF]
    const float* __restrict__ pal,         // [FID+1,4]
    const float* __restrict__ minv,        // [2]
    const float* __restrict__ rngv,        // [2]
    const int*   __restrict__ skipp)       // [1]
{
    // Unpacked tables: the float4 sBC merge lost ~2us in three separate
    // measurements (R2/R5/R14) — keep the 3-LDS form.
    __shared__ float4 sA[NF_];             // a00,a01,a10,a11
    __shared__ float2 sB[NF_];
    __shared__ float  sC[NF_];
    __shared__ float4 sP[FID_ + 1];

    const int t = threadIdx.x;
    if (t < NF_) {
        sA[t] = make_float4(A[4*t], A[4*t+1], A[4*t+2], A[4*t+3]);
        sB[t] = make_float2(Bv[2*t], Bv[2*t+1]);
        sC[t] = fcol[t];
    }
    for (int i = t; i <= FID_; i += blockDim.x)
        sP[i] = make_float4(pal[4*i], pal[4*i+1], pal[4*i+2], pal[4*i+3]);

    const float mnx = minv[0], mny = minv[1];
    const float rx  = rngv[0], ry  = rngv[1];
    const int skip  = skipp[0];
    __syncthreads();

    const int n = blockIdx.x * FLAME_BLK + t;
    float x = points[3*n + 0];
    float y = points[3*n + 1];
    float c = points[3*n + 2];

    #pragma unroll
    for (int k = 0; k < KST; k++) {
        // Per-iteration coalesced load (front-batching regressed — R2).
        // __ldcs: choices streamed once (80 MB) — evict-first spares L1/L2
        // capacity for the RED traffic.
        const int idx   = __ldcs(&choices[k * NPTS + n]);
        const float4 a  = sA[idx];
        const float2 bb = sB[idx];
        // Exact FP expression order — do not reassociate.
        const float nx = a.x * x + a.y * y + bb.x;
        const float ny = a.z * x + a.w * y + bb.y;
        c = 0.5f * (c + sC[idx]);
        x = nx; y = ny;

        if (k < skip) continue;

        // Matches XLA astype(int32): truncate toward zero, saturating, NaN->0.
        const int xb = (int)((x - mnx) * rx);
        const int yb = (int)((y - mny) * ry);
        if ((unsigned)xb < (unsigned)W_ && (unsigned)yb < (unsigned)H_) {
            const float _c = c * (float)FID_;
            const float cf = floorf(_c);
            const float t1 = _c - cf;
            const float t0 = 1.0f - t1;
            int cfi = (int)cf;  cfi = max(0, min(FID_, cfi));
            // ceil(_c) == floor(_c)+1 except when _c integral, where t1==0
            // zeroes the t1*p1 term either way -> bit-identical.
            const int cci = min(FID_, cfi + 1);
            const float4 p0 = sP[cfi];
            const float4 p1 = sP[cci];
            float4 v;
            v.x = t1 * p1.x + t0 * p0.x;
            v.y = t1 * p1.y + t0 * p0.y;
            v.z = t1 * p1.z + t0 * p0.z;
            v.w = t1 * p1.w + t0 * p0.w;
            // img[:, xb, yb]: xb indexes dim of size H (stride W), yb last dim
            red_add_v4(&g_acc[xb * W_ + yb], v);
        }
    }
}

// Loads-first / stores-last (R7 lesson: interleaving the re-zero store
// collapsed MLP, 9.4 -> 32.8us). raw0/out streaming marked evict-first
// (neutral but protects g_acc residency at zero cost).
__global__ __launch_bounds__(256) void finalize_kernel(
    const float* __restrict__ raw0,
    float* __restrict__ out) {
    const int p = blockIdx.x * blockDim.x + threadIdx.x;
    // --- all loads issue first ---
    const float4 v = g_acc[p];
    const float r0 = __ldcs(&raw0[p + 0 * H_ * W_]);
    const float r1 = __ldcs(&raw0[p + 1 * H_ * W_]);
    const float r2 = __ldcs(&raw0[p + 2 * H_ * W_]);
    const float r3 = __ldcs(&raw0[p + 3 * H_ * W_]);
    // --- then stores (evict-first: out is write-once) ---
    __stcs(&out[p + 0 * H_ * W_], v.x + r0);
    __stcs(&out[p + 1 * H_ * W_], v.y + r1);
    __stcs(&out[p + 2 * H_ * W_], v.z + r2);
    __stcs(&out[p + 3 * H_ * W_], v.w + r3);
    // Re-zero for the next invocation (replaces the 6us zeroing pass).
    g_acc[p] = make_float4(0.f, 0.f, 0.f, 0.f);
}

extern "C" void kernel_launch(void* const* d_in, const int* in_sizes, int n_in,
                              void* d_out, int out_size) {
    const float* points = (const float*)d_in[0];
    const int*   choices= (const int*)  d_in[1];
    const float* A      = (const float*)d_in[2];
    const float* b      = (const float*)d_in[3];
    const float* fcol   = (const float*)d_in[4];
    const float* pal    = (const float*)d_in[5];
    const float* minv   = (const float*)d_in[6];
    const float* rngv   = (const float*)d_in[7];
    const float* raw0   = (const float*)d_in[8];
    const int*   skip   = (const int*)  d_in[9];
    float* out = (float*)d_out;

    // No zeroing pass: g_acc starts zeroed (module load) and finalize_kernel
    // restores the all-zero state at the end of every call.
    flame_kernel<<<NPTS / FLAME_BLK, FLAME_BLK>>>(points, choices, A, b, fcol,
                                                  pal, minv, rngv, skip);
    finalize_kernel<<<(H_ * W_) / 256, 256>>>(raw0, out);
}